// round 9
// baseline (speedup 1.0000x reference)
#include <cuda_runtime.h>
#include <cuda_fp16.h>
#include <math.h>
#include <stdint.h>

#define BATCH 4096
#define T 25
#define CT 32
#define FIN 800
#define GO 64
#define H 256
#define VE 16
#define VR 12
#define KE 400
#define KR 300
#define KPE 448           /* padded K, ecc (7 chunks of 64) */
#define KPR 320           /* padded K, err (5 chunks of 64) */
#define NCHE 7
#define NCHR 5
#define NCH 12
#define KC 64             /* k per staged chunk */
#define MT 32             /* batch rows per CTA */
#define RSB 144           /* staged tile row stride, bytes */
#define ES 260            /* eg/rg row stride, floats */
#define B_ERR_OFS (256 * KPE)
#define B_TOT (256 * KPE + 256 * KPR)

/* k_main staging buffer layout (bytes) */
#define XF_OFS 0
#define BF_OFS 4608
#define SM_MAIN 66560

/* k_pre dynamic smem layout (float offsets) */
#define SWE_O 0
#define SWS_O 64
#define SM_O 80           /* sM: 3*25*64 = 4800 */
#define SU0_O 4880        /* 1600 */
#define SU1_O 6480        /* 1600 */
#define SP_O 8080         /* 4096 */
#define SQ_O 12176        /* 4096 */
#define SM_PRE_BYTES 65536

// ---------------- device scratch ----------------
__device__ __align__(16) __half g_Bf[B_TOT];   // [n][K_pad] fp16, ecc then err
__device__ float g_C[2][H];

// ---------------- helpers ----------------
__device__ __forceinline__ void mma16816(float* d, uint32_t a0, uint32_t a1,
                                         uint32_t a2, uint32_t a3,
                                         uint32_t b0, uint32_t b1) {
    asm volatile(
        "mma.sync.aligned.m16n8k16.row.col.f32.f16.f16.f32 "
        "{%0,%1,%2,%3}, {%4,%5,%6,%7}, {%8,%9}, {%0,%1,%2,%3};"
        : "+f"(d[0]), "+f"(d[1]), "+f"(d[2]), "+f"(d[3])
        : "r"(a0), "r"(a1), "r"(a2), "r"(a3), "r"(b0), "r"(b1));
}
__device__ __forceinline__ uint32_t pack_h2(__half lo, __half hi) {
    return ((uint32_t)__half_as_ushort(hi) << 16) |
           (uint32_t)__half_as_ushort(lo);
}

// ============ single precompute kernel: U/S/edges in-block + B + C ============
extern __shared__ float sdyn[];

__global__ void __launch_bounds__(256) k_pre(
    const float* __restrict__ Pe, const float* __restrict__ Pr,
    const float* __restrict__ pbe, const float* __restrict__ pbr,
    const float* __restrict__ chbe, const float* __restrict__ chbr,
    const float* __restrict__ cwe, const float* __restrict__ cbe,
    const float* __restrict__ cwr, const float* __restrict__ cbr,
    const float* __restrict__ Wche, const float* __restrict__ Wchr,
    const int* __restrict__ eie, int Ee, const int* __restrict__ eir, int Er) {
    const int tid = threadIdx.x;
    const int b = blockIdx.x;
    float* swe = sdyn + SWE_O;
    float* sws = sdyn + SWS_O;
    float* sM = sdyn + SM_O;
    float* sU0 = sdyn + SU0_O;
    float* sU1 = sdyn + SU1_O;
    float* sP = sdyn + SP_O;
    float* sQ = sdyn + SQ_O;
    const int oz = tid & 63;
    const int tg = tid >> 6;

    if (b < (VE + VR) * 4) {
        // ================= A block: node v, h-chunk =================
        const int vb = b >> 2, hb = (b & 3) * 64;
        const int br = vb >= VE;
        const int v = br ? vb - VE : vb;
        const float* P = br ? Pr : Pe;
        const float* cw = br ? cwr : cwe;
        const float* Wbr = br ? Wchr : Wche;
        const int* ei = br ? eir : eie;
        const int E = br ? Er : Ee;
        const size_t base = br ? (size_t)B_ERR_OFS : 0;
        const int KP = br ? KPR : KPE;

        // ---- edge weights ----
        if (tid < E) {
            int s = ei[tid], d = ei[E + tid];
            int degs = 0, degd = 0;
            for (int i = 0; i < E; i++) {
                int si = ei[i];
                degs += (si == s);
                degd += (si == d);
            }
            float ds = degs > 0 ? rsqrtf((float)degs) : 0.f;
            float dd = degd > 0 ? rsqrtf((float)degd) : 0.f;
            swe[tid] = -ds * dd;
        }
        __syncthreads();
        // per-thread neighbor list of v (redundant scan, deterministic)
        int cnt = 0;
        int nd[4] = {0, 0, 0, 0};
        float nw[4] = {0.f, 0.f, 0.f, 0.f};
        for (int e = 0; e < E; e++) {
            if (ei[e] == v && cnt < 4) {
                nd[cnt] = ei[E + e];
                nw[cnt] = swe[e];
                cnt++;
            }
        }

        // ---- U0/U1 in-block: M[kk][t][o] = sum_c cw[c][kk]*W[(c,t),o] ----
#pragma unroll
        for (int which = 0; which < 2; which++) {
            const float* W = Wbr + which * FIN * GO;
            float Ml[7][3];
#pragma unroll
            for (int j = 0; j < 7; j++)
                Ml[j][0] = Ml[j][1] = Ml[j][2] = 0.f;
            for (int c = 0; c < CT; c++) {
                float c0 = cw[c * 3 + 0];
                float c1 = cw[c * 3 + 1];
                float c2 = cw[c * 3 + 2];
#pragma unroll
                for (int j = 0; j < 7; j++) {
                    int t = tg + j * 4;
                    if (t < T) {
                        float w = W[(c * T + t) * GO + oz];
                        Ml[j][0] += c0 * w;
                        Ml[j][1] += c1 * w;
                        Ml[j][2] += c2 * w;
                    }
                }
            }
#pragma unroll
            for (int j = 0; j < 7; j++) {
                int t = tg + j * 4;
                if (t < T) {
                    sM[0 * 1600 + t * 64 + oz] = Ml[j][0];
                    sM[1 * 1600 + t * 64 + oz] = Ml[j][1];
                    sM[2 * 1600 + t * 64 + oz] = Ml[j][2];
                }
            }
            __syncthreads();
            float* sU = which ? sU1 : sU0;
            for (int tp = tg; tp < T; tp += 4) {
                float u = 0.f;
#pragma unroll
                for (int kk = 0; kk < 3; kk++) {
                    int t = tp - kk + 1;
                    if (t >= 0 && t < T) u += sM[kk * 1600 + t * 64 + oz];
                }
                sU[tp * 64 + oz] = u;
            }
            __syncthreads();
        }

        // ---- stage sP / sQ ----
        for (int i4 = tid; i4 < 1024; i4 += 256) {
            int oo = i4 >> 4, hl4 = (i4 & 15) * 4;
            ((float4*)sP)[i4] = *(const float4*)&P[(v * GO + oo) * H + hb + hl4];
            float4 q = make_float4(0.f, 0.f, 0.f, 0.f);
#pragma unroll
            for (int j = 0; j < 4; j++) {
                if (j < cnt) {
                    float4 pd = *(const float4*)&P[(nd[j] * GO + oo) * H + hb + hl4];
                    q.x += nw[j] * pd.x;
                    q.y += nw[j] * pd.y;
                    q.z += nw[j] * pd.z;
                    q.w += nw[j] * pd.w;
                }
            }
            ((float4*)sQ)[i4] = q;
        }
        __syncthreads();

        // ---- compute B rows, write fp16 ----
        const int hl4 = (tid & 15) * 4;
        const int tpg = tid >> 4;
        for (int tp = tpg; tp < T; tp += 16) {
            float4 acc = make_float4(0.f, 0.f, 0.f, 0.f);
#pragma unroll 16
            for (int o = 0; o < 64; o++) {
                float4 p = *(const float4*)&sP[o * 64 + hl4];
                float4 q = *(const float4*)&sQ[o * 64 + hl4];
                float u0 = sU0[tp * GO + o];
                float u1 = sU1[tp * GO + o];
                acc.x += u0 * p.x + u1 * q.x;
                acc.y += u0 * p.y + u1 * q.y;
                acc.z += u0 * p.z + u1 * q.z;
                acc.w += u0 * p.w + u1 * q.w;
            }
            const int kg = v * T + tp;
            float vals[4] = {acc.x, acc.y, acc.z, acc.w};
#pragma unroll
            for (int j = 0; j < 4; j++) {
                int n = hb + hl4 + j;
                g_Bf[base + (size_t)n * KP + kg] = __float2half_rn(vals[j]);
            }
        }
    } else if (b < (VE + VR) * 4 + 16) {
        // ================= C block =================
        const int cb = b - (VE + VR) * 4;   // 0..15
        const int br = cb >> 3;
        const int hc = cb & 7;
        const float* chb = br ? chbr : chbe;
        const float* pb = br ? pbr : pbe;
        const float* P = br ? Pr : Pe;
        const float* cb_ = br ? cbr : cbe;
        const float* Wbr = br ? Wchr : Wche;
        const int* ei = br ? eir : eie;
        const int E = br ? Er : Ee;
        const int V = br ? VR : VE;

        // edge weights + wsum
        if (tid < E) {
            int s = ei[tid], d = ei[E + tid];
            int degs = 0, degd = 0;
            for (int i = 0; i < E; i++) {
                int si = ei[i];
                degs += (si == s);
                degd += (si == d);
            }
            float ds = degs > 0 ? rsqrtf((float)degs) : 0.f;
            float dd = degd > 0 ? rsqrtf((float)degd) : 0.f;
            swe[tid] = -ds * dd;
        }
        __syncthreads();
        if (tid < 16) {
            float ws = 0.f;
            if (tid < V)
                for (int e = 0; e < E; e++)
                    if (ei[E + e] == tid) ws += swe[e];
            sws[tid] = ws;
        }

        // S0/S1 in-block: S[which][o] = sum_c cb[c]*sum_t W[(c,t),o]
        float* sS0 = sM;          // 64
        float* sS1 = sM + 64;     // 64
        float* sred = sM + 128;   // 256
        float* cfo = sM + 384;    // 64
#pragma unroll
        for (int which = 0; which < 2; which++) {
            const float* W = Wbr + which * FIN * GO;
            float acc = 0.f;
#pragma unroll
            for (int cj = 0; cj < 8; cj++) {
                int c = tg * 8 + cj;
                float s = 0.f;
#pragma unroll
                for (int t = 0; t < T; t++) s += W[(c * T + t) * GO + oz];
                acc += cb_[c] * s;
            }
            sred[tid] = acc;
            __syncthreads();
            if (tid < 64)
                (which ? sS1 : sS0)[tid] =
                    sred[tid] + sred[64 + tid] + sred[128 + tid] + sred[192 + tid];
            __syncthreads();
        }
        if (tid < 64) cfo[tid] = chb[tid] + sS0[tid];
        __syncthreads();

        // C reduction over P
        const int lane = tid & 31, rp = tid >> 5;
        const int h = hc * 32 + lane;
        const int R = V * GO;
        const int RP = R >> 3;
        float acc = 0.f;
#pragma unroll 4
        for (int r = rp * RP; r < (rp + 1) * RP; r++) {
            int o = r & 63, v = r >> 6;
            float coef = cfo[o] + sS1[o] * sws[v];
            acc += coef * P[r * H + h];
        }
        sred[tid] = acc;
        __syncthreads();
        if (tid < 32) {
            float s = pb[h];
#pragma unroll
            for (int j = 0; j < 8; j++) s += sred[j * 32 + lane];
            g_C[br][h] = s;
        }
    } else {
        // ================= zero-fill K padding of B =================
        const int NE = 256 * (KPE - KE);
        const int NR = 256 * (KPR - KR);
        __half z = __float2half_rn(0.f);
        for (int i = tid; i < NE + NR; i += 256) {
            size_t idx;
            if (i < NE) {
                int n = i / (KPE - KE), k = KE + i % (KPE - KE);
                idx = (size_t)n * KPE + k;
            } else {
                int r = i - NE;
                int n = r / (KPR - KR), k = KR + r % (KPR - KR);
                idx = (size_t)B_ERR_OFS + (size_t)n * KPR + k;
            }
            g_Bf[idx] = z;
        }
    }
}

// ---------------- main: fp16 HMMA GEMM + gated tail (unchanged from R8) ------
extern __shared__ char smx[];

__global__ void __launch_bounds__(256, 1)
k_main(const float* __restrict__ ecc, const float* __restrict__ err,
       const float* __restrict__ attnW, const float* __restrict__ attnb,
       const float* __restrict__ fc2W, const float* __restrict__ fc2b,
       float* __restrict__ out) {
    char* sXf = smx + XF_OFS;
    char* sBf = smx + BF_OFS;

    const int tid = threadIdx.x;
    const int wid = tid >> 5;
    const int lane = tid & 31;
    const int g = lane >> 2;
    const int i2 = (lane & 3) * 2;
    const int ns = wid * 32;
    const int rb = blockIdx.x * MT;

    float de[2][4][4], dr[2][4][4];
#pragma unroll
    for (int mt = 0; mt < 2; mt++)
#pragma unroll
        for (int nt = 0; nt < 4; nt++)
#pragma unroll
            for (int j = 0; j < 4; j++) {
                de[mt][nt][j] = 0.f;
                dr[mt][nt][j] = 0.f;
            }

#pragma unroll 1
    for (int c = 0; c < NCH; c++) {
        const int br = (c >= NCHE);
        const int cc = br ? c - NCHE : c;
        const float* X = br ? err : ecc;
        const int Kreal = br ? KR : KE;
        const int KP = br ? KPR : KPE;
        const char* gB = (const char*)(g_Bf + (br ? B_ERR_OFS : 0));

        __syncthreads();
#pragma unroll
        for (int it = 0; it < 2; it++) {
            int idx = tid + it * 256;
            int row = idx >> 4, kq = idx & 15;
            int k = cc * KC + kq * 4;
            float4 x = make_float4(0.f, 0.f, 0.f, 0.f);
            if (k < Kreal)
                x = *(const float4*)&X[(size_t)(rb + row) * Kreal + k];
            *(uint2*)(sXf + row * RSB + kq * 8) =
                make_uint2(pack_h2(__float2half_rn(x.x), __float2half_rn(x.y)),
                           pack_h2(__float2half_rn(x.z), __float2half_rn(x.w)));
        }
#pragma unroll
        for (int it = 0; it < 8; it++) {
            int idx = tid + it * 256;
            int n = idx >> 3, q = idx & 7;
            size_t gb = (size_t)n * KP * 2 + (size_t)cc * KC * 2 + q * 16;
            *(uint4*)(sBf + n * RSB + q * 16) = *(const uint4*)(gB + gb);
        }
        __syncthreads();

        float (*d)[4][4] = br ? dr : de;
#pragma unroll
        for (int ks = 0; ks < 4; ks++) {
            const int kb = ks * 32 + i2 * 2;
            uint32_t a[2][4];
#pragma unroll
            for (int mt = 0; mt < 2; mt++) {
                const char* ap = sXf + (mt * 16 + g) * RSB + kb;
                a[mt][0] = *(const uint32_t*)ap;
                a[mt][1] = *(const uint32_t*)(ap + 8 * RSB);
                a[mt][2] = *(const uint32_t*)(ap + 16);
                a[mt][3] = *(const uint32_t*)(ap + 8 * RSB + 16);
            }
#pragma unroll
            for (int nt = 0; nt < 4; nt++) {
                const char* bp = sBf + (ns + nt * 8 + g) * RSB + kb;
                uint32_t b0 = *(const uint32_t*)bp;
                uint32_t b1 = *(const uint32_t*)(bp + 16);
#pragma unroll
                for (int mt = 0; mt < 2; mt++)
                    mma16816(d[mt][nt], a[mt][0], a[mt][1], a[mt][2], a[mt][3],
                             b0, b1);
            }
        }
    }
    __syncthreads();

    float* eg = (float*)smx;
    float* rg = eg + MT * ES;
#pragma unroll
    for (int mt = 0; mt < 2; mt++)
#pragma unroll
        for (int nt = 0; nt < 4; nt++) {
            int row = mt * 16 + g;
            int col = ns + nt * 8 + i2;
            eg[row * ES + col] = de[mt][nt][0];
            eg[row * ES + col + 1] = de[mt][nt][1];
            eg[(row + 8) * ES + col] = de[mt][nt][2];
            eg[(row + 8) * ES + col + 1] = de[mt][nt][3];
            rg[row * ES + col] = dr[mt][nt][0];
            rg[row * ES + col + 1] = dr[mt][nt][1];
            rg[(row + 8) * ES + col] = dr[mt][nt][2];
            rg[(row + 8) * ES + col + 1] = dr[mt][nt][3];
        }
    __syncthreads();

    const float attnb_v = attnb[0];
    const float fc2b_v = fc2b[0];
    for (int r = wid * 4; r < wid * 4 + 4; r++) {
        const float* egr = eg + r * ES;
        const float* rgr = rg + r * ES;
        float p = 0.f;
#pragma unroll
        for (int j = lane; j < H; j += 32) {
            float ev = egr[j] + g_C[0][j];
            float rv = rgr[j] + g_C[1][j];
            p += tanhf(ev + rv) * attnW[j];
        }
#pragma unroll
        for (int o = 16; o; o >>= 1) p += __shfl_xor_sync(0xffffffffu, p, o);
        float attn = 1.f / (1.f + expf(-(p + attnb_v)));
        float q = 0.f;
#pragma unroll
        for (int j = lane; j < H; j += 32) {
            float ev = egr[j] + g_C[0][j];
            float rv = rgr[j] + g_C[1][j];
            float f = attn * ev + (1.f - attn) * rv;
            q += fmaxf(f, 0.f) * fc2W[j];
        }
#pragma unroll
        for (int o = 16; o; o >>= 1) q += __shfl_xor_sync(0xffffffffu, q, o);
        if (lane == 0) out[rb + r] = 1.f / (1.f + expf(-(q + fc2b_v)));
    }
}

// ---------------- launch ----------------
extern "C" void kernel_launch(void* const* d_in, const int* in_sizes, int n_in,
                              void* d_out, int out_size) {
    const float* ecc = (const float*)d_in[0];
    const float* err = (const float*)d_in[1];
    const float* conv_ecc_w = (const float*)d_in[2];
    const float* conv_ecc_b = (const float*)d_in[3];
    const float* conv_err_w = (const float*)d_in[4];
    const float* conv_err_b = (const float*)d_in[5];
    const float* cheb_ecc_W = (const float*)d_in[6];
    const float* cheb_ecc_b = (const float*)d_in[7];
    const float* cheb_err_W = (const float*)d_in[8];
    const float* cheb_err_b = (const float*)d_in[9];
    const float* ecc_proj_W = (const float*)d_in[10];
    const float* ecc_proj_b = (const float*)d_in[11];
    const float* err_proj_W = (const float*)d_in[12];
    const float* err_proj_b = (const float*)d_in[13];
    const float* attn_W = (const float*)d_in[14];
    const float* attn_b = (const float*)d_in[15];
    const float* fc2_W = (const float*)d_in[16];
    const float* fc2_b = (const float*)d_in[17];
    const int* ei_ecc = (const int*)d_in[18];
    const int* ei_err = (const int*)d_in[19];
    const int Ee = in_sizes[18] / 2;
    const int Er = in_sizes[19] / 2;

    cudaFuncSetAttribute(k_pre, cudaFuncAttributeMaxDynamicSharedMemorySize,
                         SM_PRE_BYTES);
    k_pre<<<(VE + VR) * 4 + 17, 256, SM_PRE_BYTES>>>(
        ecc_proj_W, err_proj_W, ecc_proj_b, err_proj_b,
        cheb_ecc_b, cheb_err_b,
        conv_ecc_w, conv_ecc_b, conv_err_w, conv_err_b,
        cheb_ecc_W, cheb_err_W, ei_ecc, Ee, ei_err, Er);

    cudaFuncSetAttribute(k_main, cudaFuncAttributeMaxDynamicSharedMemorySize,
                         SM_MAIN);
    k_main<<<BATCH / MT, 256, SM_MAIN>>>(ecc, err, attn_W, attn_b,
                                         fc2_W, fc2_b, (float*)d_out);
}

// round 10
// speedup vs baseline: 1.3900x; 1.3900x over previous
#include <cuda_runtime.h>
#include <cuda_fp16.h>
#include <math.h>
#include <stdint.h>

#define BATCH 4096
#define T 25
#define CT 32
#define FIN 800
#define GO 64
#define H 256
#define VE 16
#define VR 12
#define KE 400
#define KR 300
#define KPE 448           /* padded K, ecc (7 chunks of 64) */
#define KPR 320           /* padded K, err (5 chunks of 64) */
#define NCHE 7
#define NCHR 5
#define NCH 12
#define KC 64             /* k per staged chunk */
#define MT 16             /* batch rows per CTA */
#define RSB 144           /* staged tile row stride, bytes */
#define ES 260            /* eg/rg row stride, floats */
#define B_ERR_OFS (256 * KPE)
#define B_TOT (256 * KPE + 256 * KPR)

/* k_main staging buffer layout (bytes): X fp16 @0 (16*144), B fp16 @2304 */
#define XF_OFS 0
#define BF_OFS 2304
#define SM_MAIN 39168     /* max(2304+36864 staging, 2*16*260*4 = 33280) */

// ---------------- device scratch ----------------
__device__ float g_U[4][T * GO];
__device__ float g_S[4][GO];
__device__ float g_we[2][64];
__device__ float g_wsum[2][16];
__device__ int   g_nbrd[2][16][8];
__device__ float g_nbrw[2][16][8];
__device__ int   g_ncnt[2][16];
__device__ __align__(16) __half g_Bf[B_TOT];   // [n][K_pad] fp16, ecc then err
__device__ float g_C[2][H];

// ---------------- helpers ----------------
__device__ __forceinline__ void mma16816(float* d, uint32_t a0, uint32_t a1,
                                         uint32_t a2, uint32_t a3,
                                         uint32_t b0, uint32_t b1) {
    asm volatile(
        "mma.sync.aligned.m16n8k16.row.col.f32.f16.f16.f32 "
        "{%0,%1,%2,%3}, {%4,%5,%6,%7}, {%8,%9}, {%0,%1,%2,%3};"
        : "+f"(d[0]), "+f"(d[1]), "+f"(d[2]), "+f"(d[3])
        : "r"(a0), "r"(a1), "r"(a2), "r"(a3), "r"(b0), "r"(b1));
}
__device__ __forceinline__ uint32_t pack_h2(__half lo, __half hi) {
    return ((uint32_t)__half_as_ushort(hi) << 16) |
           (uint32_t)__half_as_ushort(lo);
}

// ---------------- precompute: U, S, edges, nbr lists (R8) ------------
__global__ void __launch_bounds__(256) k_prep(
    const float* __restrict__ cwe, const float* __restrict__ cbe,
    const float* __restrict__ cwr, const float* __restrict__ cbr,
    const float* __restrict__ Wche, const float* __restrict__ Wchr,
    const int* __restrict__ eie, int Ee, const int* __restrict__ eir, int Er) {
    __shared__ float red[256];
    const int b = blockIdx.x;
    const int tid = threadIdx.x;
    const int o = tid & 63;
    const int cc = tid >> 6;

    if (b < 4 * T) {
        const int mat = b / T, tp = b % T;
        const int branch = mat >> 1, which = mat & 1;
        const float* cw = branch ? cwr : cwe;
        const float* W = (branch ? Wchr : Wche) + which * FIN * GO;
        float acc = 0.f;
#pragma unroll
        for (int k = 0; k < 3; k++) {
            int t = tp - k + 1;
            if (t >= 0 && t < T) {
#pragma unroll
                for (int cj = 0; cj < 8; cj++) {
                    int c = cc * 8 + cj;
                    acc += cw[c * 3 + k] * W[(c * T + t) * GO + o];
                }
            }
        }
        red[tid] = acc;
        __syncthreads();
        if (tid < 64)
            g_U[mat][tp * GO + tid] =
                red[tid] + red[64 + tid] + red[128 + tid] + red[192 + tid];
    } else if (b < 4 * T + 4) {
        const int mat = b - 4 * T;
        const int branch = mat >> 1, which = mat & 1;
        const float* cb = branch ? cbr : cbe;
        const float* W = (branch ? Wchr : Wche) + which * FIN * GO;
        float acc = 0.f;
#pragma unroll
        for (int cj = 0; cj < 8; cj++) {
            int c = cc * 8 + cj;
            float s = 0.f;
#pragma unroll
            for (int t = 0; t < T; t++) s += W[(c * T + t) * GO + o];
            acc += cb[c] * s;
        }
        red[tid] = acc;
        __syncthreads();
        if (tid < 64)
            g_S[mat][tid] =
                red[tid] + red[64 + tid] + red[128 + tid] + red[192 + tid];
    } else {
        int t = tid;
        for (int g = 0; g < 2; g++) {
            const int* ei = g ? eir : eie;
            int E = g ? Er : Ee;
            int V = g ? VR : VE;
            if (t < E) {
                int s = ei[t], d = ei[E + t];
                int degs = 0, degd = 0;
                for (int i = 0; i < E; i++) {
                    int si = ei[i];
                    degs += (si == s);
                    degd += (si == d);
                }
                float ds = degs > 0 ? rsqrtf((float)degs) : 0.f;
                float dd = degd > 0 ? rsqrtf((float)degd) : 0.f;
                g_we[g][t] = -ds * dd;
            }
            __syncthreads();
            if (t < 16) {
                float ws = 0.f;
                int cnt = 0;
                if (t < V) {
                    for (int e = 0; e < E; e++) {
                        if (ei[E + e] == t) ws += g_we[g][e];
                        if (ei[e] == t && cnt < 8) {
                            g_nbrd[g][t][cnt] = ei[E + e];
                            g_nbrw[g][t][cnt] = g_we[g][e];
                            cnt++;
                        }
                    }
                }
                g_wsum[g][t] = ws;
                g_ncnt[g][t] = cnt;
            }
            __syncthreads();
        }
    }
}

// ------- precompute: B = collapsed weights as fp16 [n][K_pad], + C (R8) -------
__global__ void __launch_bounds__(256) k_AC(
    const float* __restrict__ Pe, const float* __restrict__ Pr,
    const float* __restrict__ pbe, const float* __restrict__ pbr,
    const float* __restrict__ chbe, const float* __restrict__ chbr) {
    __shared__ float sP[64 * 64];
    __shared__ float sQ[64 * 64];
    __shared__ float sU0[T * GO];
    __shared__ float sU1[T * GO];
    const int tid = threadIdx.x;
    const int b = blockIdx.x;

    if (b < (VE + VR) * 4) {
        const int vb = b >> 2, hb = (b & 3) * 64;
        const int br = vb >= VE;
        const int v = br ? vb - VE : vb;
        const float* P = br ? Pr : Pe;
        const size_t base = br ? (size_t)B_ERR_OFS : 0;
        const int KP = br ? KPR : KPE;

        {
            const float4* U0 = (const float4*)g_U[2 * br];
            const float4* U1 = (const float4*)g_U[2 * br + 1];
            float4* s0 = (float4*)sU0;
            float4* s1 = (float4*)sU1;
            for (int i = tid; i < T * GO / 4; i += 256) {
                s0[i] = U0[i];
                s1[i] = U1[i];
            }
        }
        const int cnt = g_ncnt[br][v];
        int nd[4];
        float nw[4];
#pragma unroll
        for (int j = 0; j < 4; j++) {
            nd[j] = (j < cnt) ? g_nbrd[br][v][j] : 0;
            nw[j] = (j < cnt) ? g_nbrw[br][v][j] : 0.f;
        }
        for (int i4 = tid; i4 < 1024; i4 += 256) {
            int oo = i4 >> 4, hl4 = (i4 & 15) * 4;
            ((float4*)sP)[i4] = *(const float4*)&P[(v * GO + oo) * H + hb + hl4];
            float4 q = make_float4(0.f, 0.f, 0.f, 0.f);
#pragma unroll
            for (int j = 0; j < 4; j++) {
                if (j < cnt) {
                    float4 pd = *(const float4*)&P[(nd[j] * GO + oo) * H + hb + hl4];
                    q.x += nw[j] * pd.x;
                    q.y += nw[j] * pd.y;
                    q.z += nw[j] * pd.z;
                    q.w += nw[j] * pd.w;
                }
            }
            ((float4*)sQ)[i4] = q;
        }
        __syncthreads();

        const int hl4 = (tid & 15) * 4;
        const int tpg = tid >> 4;
        for (int tp = tpg; tp < T; tp += 16) {
            float4 acc = make_float4(0.f, 0.f, 0.f, 0.f);
#pragma unroll 16
            for (int o = 0; o < 64; o++) {
                float4 p = *(const float4*)&sP[o * 64 + hl4];
                float4 q = *(const float4*)&sQ[o * 64 + hl4];
                float u0 = sU0[tp * GO + o];
                float u1 = sU1[tp * GO + o];
                acc.x += u0 * p.x + u1 * q.x;
                acc.y += u0 * p.y + u1 * q.y;
                acc.z += u0 * p.z + u1 * q.z;
                acc.w += u0 * p.w + u1 * q.w;
            }
            const int kg = v * T + tp;
            float vals[4] = {acc.x, acc.y, acc.z, acc.w};
#pragma unroll
            for (int j = 0; j < 4; j++) {
                int n = hb + hl4 + j;
                g_Bf[base + (size_t)n * KP + kg] = __float2half_rn(vals[j]);
            }
        }
    } else if (b == (VE + VR) * 4 + 16) {
        const int NE = 256 * (KPE - KE);
        const int NR = 256 * (KPR - KR);
        __half z = __float2half_rn(0.f);
        for (int i = tid; i < NE + NR; i += 256) {
            size_t idx;
            if (i < NE) {
                int n = i / (KPE - KE), k = KE + i % (KPE - KE);
                idx = (size_t)n * KPE + k;
            } else {
                int r = i - NE;
                int n = r / (KPR - KR), k = KR + r % (KPR - KR);
                idx = (size_t)B_ERR_OFS + (size_t)n * KPR + k;
            }
            g_Bf[idx] = z;
        }
    } else {
        const int cb = b - (VE + VR) * 4;
        const int br = cb >> 3;
        const int hc = cb & 7;
        const float* chb = br ? chbr : chbe;
        const float* pb = br ? pbr : pbe;
        const float* P = br ? Pr : Pe;
        const int V = br ? VR : VE;
        float* cfo = sP;
        float* s1v = sP + 64;
        float* ws = sP + 128;
        float* red = sP + 160;

        if (tid < 64) {
            cfo[tid] = chb[tid] + g_S[2 * br][tid];
            s1v[tid] = g_S[2 * br + 1][tid];
        }
        if (tid < 16) ws[tid] = g_wsum[br][tid];
        __syncthreads();

        const int lane = tid & 31, rp = tid >> 5;
        const int h = hc * 32 + lane;
        const int R = V * GO;
        const int RP = R >> 3;
        float acc = 0.f;
#pragma unroll 4
        for (int r = rp * RP; r < (rp + 1) * RP; r++) {
            int o = r & 63, v = r >> 6;
            float coef = cfo[o] + s1v[o] * ws[v];
            acc += coef * P[r * H + h];
        }
        red[tid] = acc;
        __syncthreads();
        if (tid < 32) {
            float s = pb[h];
#pragma unroll
            for (int j = 0; j < 8; j++) s += red[j * 32 + lane];
            g_C[br][h] = s;
        }
    }
}

// ------- main: fp16 HMMA GEMM, MT=16, 2 CTAs/SM, + gated tail -------
extern __shared__ char smx[];

__global__ void __launch_bounds__(256, 2)
k_main(const float* __restrict__ ecc, const float* __restrict__ err,
       const float* __restrict__ attnW, const float* __restrict__ attnb,
       const float* __restrict__ fc2W, const float* __restrict__ fc2b,
       float* __restrict__ out) {
    char* sXf = smx + XF_OFS;
    char* sBf = smx + BF_OFS;

    const int tid = threadIdx.x;
    const int wid = tid >> 5;
    const int lane = tid & 31;
    const int g = lane >> 2;        // fragment group row/col
    const int i2 = (lane & 3) * 2;  // fragment k pair base
    const int ns = wid * 32;        // this warp's n slice
    const int rb = blockIdx.x * MT;

    float de[4][4], dr[4][4];
#pragma unroll
    for (int nt = 0; nt < 4; nt++)
#pragma unroll
        for (int j = 0; j < 4; j++) {
            de[nt][j] = 0.f;
            dr[nt][j] = 0.f;
        }

#pragma unroll 1
    for (int c = 0; c < NCH; c++) {
        const int br = (c >= NCHE);
        const int cc = br ? c - NCHE : c;
        const float* X = br ? err : ecc;
        const int Kreal = br ? KR : KE;
        const int KP = br ? KPR : KPE;
        const char* gB = (const char*)(g_Bf + (br ? B_ERR_OFS : 0));

        __syncthreads();   // previous chunk's mma reads done
        // ---- stage X chunk: 16 rows x 64 k, fp32 -> fp16 (256 items) ----
        {
            int row = tid >> 4, kq = tid & 15;
            int k = cc * KC + kq * 4;
            float4 x = make_float4(0.f, 0.f, 0.f, 0.f);
            if (k < Kreal)
                x = *(const float4*)&X[(size_t)(rb + row) * Kreal + k];
            *(uint2*)(sXf + row * RSB + kq * 8) =
                make_uint2(pack_h2(__float2half_rn(x.x), __float2half_rn(x.y)),
                           pack_h2(__float2half_rn(x.z), __float2half_rn(x.w)));
        }
        // ---- stage B chunk: 256 n x 64 k fp16, 16B copies ----
#pragma unroll
        for (int it = 0; it < 8; it++) {
            int idx = tid + it * 256;
            int n = idx >> 3, q = idx & 7;
            size_t gb = (size_t)n * KP * 2 + (size_t)cc * KC * 2 + q * 16;
            *(uint4*)(sBf + n * RSB + q * 16) = *(const uint4*)(gB + gb);
        }
        __syncthreads();

        float (*d)[4] = br ? dr : de;
        // ---- 4 k-steps of m16n8k16 fp16 ----
#pragma unroll
        for (int ks = 0; ks < 4; ks++) {
            const int kb = ks * 32 + i2 * 2;
            const char* ap = sXf + g * RSB + kb;
            uint32_t a0 = *(const uint32_t*)ap;
            uint32_t a1 = *(const uint32_t*)(ap + 8 * RSB);
            uint32_t a2 = *(const uint32_t*)(ap + 16);
            uint32_t a3 = *(const uint32_t*)(ap + 8 * RSB + 16);
#pragma unroll
            for (int nt = 0; nt < 4; nt++) {
                const char* bp = sBf + (ns + nt * 8 + g) * RSB + kb;
                uint32_t b0 = *(const uint32_t*)bp;
                uint32_t b1 = *(const uint32_t*)(bp + 16);
                mma16816(d[nt], a0, a1, a2, a3, b0, b1);
            }
        }
    }
    __syncthreads();

    // -------- write fragments to smem (reuse staging buffer) --------
    float* eg = (float*)smx;
    float* rg = eg + MT * ES;
#pragma unroll
    for (int nt = 0; nt < 4; nt++) {
        int row = g;
        int col = ns + nt * 8 + i2;
        eg[row * ES + col] = de[nt][0];
        eg[row * ES + col + 1] = de[nt][1];
        eg[(row + 8) * ES + col] = de[nt][2];
        eg[(row + 8) * ES + col + 1] = de[nt][3];
        rg[row * ES + col] = dr[nt][0];
        rg[row * ES + col + 1] = dr[nt][1];
        rg[(row + 8) * ES + col] = dr[nt][2];
        rg[(row + 8) * ES + col + 1] = dr[nt][3];
    }
    __syncthreads();

    // -------- gated tail: 1 warp per 2 rows --------
    const float attnb_v = attnb[0];
    const float fc2b_v = fc2b[0];
    for (int r = wid * 2; r < wid * 2 + 2; r++) {
        const float* egr = eg + r * ES;
        const float* rgr = rg + r * ES;
        float p = 0.f;
#pragma unroll
        for (int j = lane; j < H; j += 32) {
            float ev = egr[j] + g_C[0][j];
            float rv = rgr[j] + g_C[1][j];
            p += tanhf(ev + rv) * attnW[j];
        }
#pragma unroll
        for (int o = 16; o; o >>= 1) p += __shfl_xor_sync(0xffffffffu, p, o);
        float attn = 1.f / (1.f + expf(-(p + attnb_v)));
        float q = 0.f;
#pragma unroll
        for (int j = lane; j < H; j += 32) {
            float ev = egr[j] + g_C[0][j];
            float rv = rgr[j] + g_C[1][j];
            float f = attn * ev + (1.f - attn) * rv;
            q += fmaxf(f, 0.f) * fc2W[j];
        }
#pragma unroll
        for (int o = 16; o; o >>= 1) q += __shfl_xor_sync(0xffffffffu, q, o);
        if (lane == 0) out[rb + r] = 1.f / (1.f + expf(-(q + fc2b_v)));
    }
}

// ---------------- launch ----------------
extern "C" void kernel_launch(void* const* d_in, const int* in_sizes, int n_in,
                              void* d_out, int out_size) {
    const float* ecc = (const float*)d_in[0];
    const float* err = (const float*)d_in[1];
    const float* conv_ecc_w = (const float*)d_in[2];
    const float* conv_ecc_b = (const float*)d_in[3];
    const float* conv_err_w = (const float*)d_in[4];
    const float* conv_err_b = (const float*)d_in[5];
    const float* cheb_ecc_W = (const float*)d_in[6];
    const float* cheb_ecc_b = (const float*)d_in[7];
    const float* cheb_err_W = (const float*)d_in[8];
    const float* cheb_err_b = (const float*)d_in[9];
    const float* ecc_proj_W = (const float*)d_in[10];
    const float* ecc_proj_b = (const float*)d_in[11];
    const float* err_proj_W = (const float*)d_in[12];
    const float* err_proj_b = (const float*)d_in[13];
    const float* attn_W = (const float*)d_in[14];
    const float* attn_b = (const float*)d_in[15];
    const float* fc2_W = (const float*)d_in[16];
    const float* fc2_b = (const float*)d_in[17];
    const int* ei_ecc = (const int*)d_in[18];
    const int* ei_err = (const int*)d_in[19];
    const int Ee = in_sizes[18] / 2;
    const int Er = in_sizes[19] / 2;

    k_prep<<<4 * T + 5, 256>>>(conv_ecc_w, conv_ecc_b, conv_err_w, conv_err_b,
                               cheb_ecc_W, cheb_err_W, ei_ecc, Ee, ei_err, Er);
    k_AC<<<(VE + VR) * 4 + 17, 256>>>(ecc_proj_W, err_proj_W,
                                      ecc_proj_b, err_proj_b,
                                      cheb_ecc_b, cheb_err_b);

    cudaFuncSetAttribute(k_main, cudaFuncAttributeMaxDynamicSharedMemorySize,
                         SM_MAIN);
    k_main<<<BATCH / MT, 256, SM_MAIN>>>(ecc, err, attn_W, attn_b,
                                         fc2_W, fc2_b, (float*)d_out);
}

// round 11
// speedup vs baseline: 1.4610x; 1.0511x over previous
#include <cuda_runtime.h>
#include <cuda_fp16.h>
#include <math.h>
#include <stdint.h>

#define BATCH 4096
#define T 25
#define CT 32
#define FIN 800
#define GO 64
#define H 256
#define VE 16
#define VR 12
#define KE 400
#define KR 300
#define KPE 448           /* padded K, ecc (7 chunks of 64) */
#define KPR 320           /* padded K, err (5 chunks of 64) */
#define NCHE 7
#define NCHR 5
#define NCH 12
#define KC 64             /* k per staged chunk */
#define MT 32             /* batch rows per CTA */
#define NTHR 512          /* threads per k_main CTA (16 warps) */
#define RSB 144           /* staged tile row stride, bytes */
#define ES 260            /* eg/rg row stride, floats */
#define B_ERR_OFS (256 * KPE)
#define B_TOT (256 * KPE + 256 * KPR)

/* k_main staging buffer layout (bytes): X fp16 @0 (32*144), B fp16 @4608 */
#define XF_OFS 0
#define BF_OFS 4608
#define SM_MAIN 66560     /* max(4608+36864 staging, 2*32*260*4 = 66560) */

// ---------------- device scratch ----------------
__device__ float g_U[4][T * GO];
__device__ float g_S[4][GO];
__device__ float g_we[2][64];
__device__ float g_wsum[2][16];
__device__ int   g_nbrd[2][16][8];
__device__ float g_nbrw[2][16][8];
__device__ int   g_ncnt[2][16];
__device__ __align__(16) __half g_Bf[B_TOT];   // [n][K_pad] fp16, ecc then err
__device__ float g_C[2][H];

// ---------------- helpers ----------------
__device__ __forceinline__ void mma16816(float* d, uint32_t a0, uint32_t a1,
                                         uint32_t a2, uint32_t a3,
                                         uint32_t b0, uint32_t b1) {
    asm volatile(
        "mma.sync.aligned.m16n8k16.row.col.f32.f16.f16.f32 "
        "{%0,%1,%2,%3}, {%4,%5,%6,%7}, {%8,%9}, {%0,%1,%2,%3};"
        : "+f"(d[0]), "+f"(d[1]), "+f"(d[2]), "+f"(d[3])
        : "r"(a0), "r"(a1), "r"(a2), "r"(a3), "r"(b0), "r"(b1));
}
__device__ __forceinline__ uint32_t pack_h2(__half lo, __half hi) {
    return ((uint32_t)__half_as_ushort(hi) << 16) |
           (uint32_t)__half_as_ushort(lo);
}

// ---------------- precompute: U, S, edges, nbr lists (R8) ------------
__global__ void __launch_bounds__(256) k_prep(
    const float* __restrict__ cwe, const float* __restrict__ cbe,
    const float* __restrict__ cwr, const float* __restrict__ cbr,
    const float* __restrict__ Wche, const float* __restrict__ Wchr,
    const int* __restrict__ eie, int Ee, const int* __restrict__ eir, int Er) {
    __shared__ float red[256];
    const int b = blockIdx.x;
    const int tid = threadIdx.x;
    const int o = tid & 63;
    const int cc = tid >> 6;

    if (b < 4 * T) {
        const int mat = b / T, tp = b % T;
        const int branch = mat >> 1, which = mat & 1;
        const float* cw = branch ? cwr : cwe;
        const float* W = (branch ? Wchr : Wche) + which * FIN * GO;
        float acc = 0.f;
#pragma unroll
        for (int k = 0; k < 3; k++) {
            int t = tp - k + 1;
            if (t >= 0 && t < T) {
#pragma unroll
                for (int cj = 0; cj < 8; cj++) {
                    int c = cc * 8 + cj;
                    acc += cw[c * 3 + k] * W[(c * T + t) * GO + o];
                }
            }
        }
        red[tid] = acc;
        __syncthreads();
        if (tid < 64)
            g_U[mat][tp * GO + tid] =
                red[tid] + red[64 + tid] + red[128 + tid] + red[192 + tid];
    } else if (b < 4 * T + 4) {
        const int mat = b - 4 * T;
        const int branch = mat >> 1, which = mat & 1;
        const float* cb = branch ? cbr : cbe;
        const float* W = (branch ? Wchr : Wche) + which * FIN * GO;
        float acc = 0.f;
#pragma unroll
        for (int cj = 0; cj < 8; cj++) {
            int c = cc * 8 + cj;
            float s = 0.f;
#pragma unroll
            for (int t = 0; t < T; t++) s += W[(c * T + t) * GO + o];
            acc += cb[c] * s;
        }
        red[tid] = acc;
        __syncthreads();
        if (tid < 64)
            g_S[mat][tid] =
                red[tid] + red[64 + tid] + red[128 + tid] + red[192 + tid];
    } else {
        int t = tid;
        for (int g = 0; g < 2; g++) {
            const int* ei = g ? eir : eie;
            int E = g ? Er : Ee;
            int V = g ? VR : VE;
            if (t < E) {
                int s = ei[t], d = ei[E + t];
                int degs = 0, degd = 0;
                for (int i = 0; i < E; i++) {
                    int si = ei[i];
                    degs += (si == s);
                    degd += (si == d);
                }
                float ds = degs > 0 ? rsqrtf((float)degs) : 0.f;
                float dd = degd > 0 ? rsqrtf((float)degd) : 0.f;
                g_we[g][t] = -ds * dd;
            }
            __syncthreads();
            if (t < 16) {
                float ws = 0.f;
                int cnt = 0;
                if (t < V) {
                    for (int e = 0; e < E; e++) {
                        if (ei[E + e] == t) ws += g_we[g][e];
                        if (ei[e] == t && cnt < 8) {
                            g_nbrd[g][t][cnt] = ei[E + e];
                            g_nbrw[g][t][cnt] = g_we[g][e];
                            cnt++;
                        }
                    }
                }
                g_wsum[g][t] = ws;
                g_ncnt[g][t] = cnt;
            }
            __syncthreads();
        }
    }
}

// ------- precompute: B = collapsed weights as fp16 [n][K_pad], + C (R8) -------
__global__ void __launch_bounds__(256) k_AC(
    const float* __restrict__ Pe, const float* __restrict__ Pr,
    const float* __restrict__ pbe, const float* __restrict__ pbr,
    const float* __restrict__ chbe, const float* __restrict__ chbr) {
    __shared__ float sP[64 * 64];
    __shared__ float sQ[64 * 64];
    __shared__ float sU0[T * GO];
    __shared__ float sU1[T * GO];
    const int tid = threadIdx.x;
    const int b = blockIdx.x;

    if (b < (VE + VR) * 4) {
        const int vb = b >> 2, hb = (b & 3) * 64;
        const int br = vb >= VE;
        const int v = br ? vb - VE : vb;
        const float* P = br ? Pr : Pe;
        const size_t base = br ? (size_t)B_ERR_OFS : 0;
        const int KP = br ? KPR : KPE;

        {
            const float4* U0 = (const float4*)g_U[2 * br];
            const float4* U1 = (const float4*)g_U[2 * br + 1];
            float4* s0 = (float4*)sU0;
            float4* s1 = (float4*)sU1;
            for (int i = tid; i < T * GO / 4; i += 256) {
                s0[i] = U0[i];
                s1[i] = U1[i];
            }
        }
        const int cnt = g_ncnt[br][v];
        int nd[4];
        float nw[4];
#pragma unroll
        for (int j = 0; j < 4; j++) {
            nd[j] = (j < cnt) ? g_nbrd[br][v][j] : 0;
            nw[j] = (j < cnt) ? g_nbrw[br][v][j] : 0.f;
        }
        for (int i4 = tid; i4 < 1024; i4 += 256) {
            int oo = i4 >> 4, hl4 = (i4 & 15) * 4;
            ((float4*)sP)[i4] = *(const float4*)&P[(v * GO + oo) * H + hb + hl4];
            float4 q = make_float4(0.f, 0.f, 0.f, 0.f);
#pragma unroll
            for (int j = 0; j < 4; j++) {
                if (j < cnt) {
                    float4 pd = *(const float4*)&P[(nd[j] * GO + oo) * H + hb + hl4];
                    q.x += nw[j] * pd.x;
                    q.y += nw[j] * pd.y;
                    q.z += nw[j] * pd.z;
                    q.w += nw[j] * pd.w;
                }
            }
            ((float4*)sQ)[i4] = q;
        }
        __syncthreads();

        const int hl4 = (tid & 15) * 4;
        const int tpg = tid >> 4;
        for (int tp = tpg; tp < T; tp += 16) {
            float4 acc = make_float4(0.f, 0.f, 0.f, 0.f);
#pragma unroll 16
            for (int o = 0; o < 64; o++) {
                float4 p = *(const float4*)&sP[o * 64 + hl4];
                float4 q = *(const float4*)&sQ[o * 64 + hl4];
                float u0 = sU0[tp * GO + o];
                float u1 = sU1[tp * GO + o];
                acc.x += u0 * p.x + u1 * q.x;
                acc.y += u0 * p.y + u1 * q.y;
                acc.z += u0 * p.z + u1 * q.z;
                acc.w += u0 * p.w + u1 * q.w;
            }
            const int kg = v * T + tp;
            float vals[4] = {acc.x, acc.y, acc.z, acc.w};
#pragma unroll
            for (int j = 0; j < 4; j++) {
                int n = hb + hl4 + j;
                g_Bf[base + (size_t)n * KP + kg] = __float2half_rn(vals[j]);
            }
        }
    } else if (b == (VE + VR) * 4 + 16) {
        const int NE = 256 * (KPE - KE);
        const int NR = 256 * (KPR - KR);
        __half z = __float2half_rn(0.f);
        for (int i = tid; i < NE + NR; i += 256) {
            size_t idx;
            if (i < NE) {
                int n = i / (KPE - KE), k = KE + i % (KPE - KE);
                idx = (size_t)n * KPE + k;
            } else {
                int r = i - NE;
                int n = r / (KPR - KR), k = KR + r % (KPR - KR);
                idx = (size_t)B_ERR_OFS + (size_t)n * KPR + k;
            }
            g_Bf[idx] = z;
        }
    } else {
        const int cb = b - (VE + VR) * 4;
        const int br = cb >> 3;
        const int hc = cb & 7;
        const float* chb = br ? chbr : chbe;
        const float* pb = br ? pbr : pbe;
        const float* P = br ? Pr : Pe;
        const int V = br ? VR : VE;
        float* cfo = sP;
        float* s1v = sP + 64;
        float* ws = sP + 128;
        float* red = sP + 160;

        if (tid < 64) {
            cfo[tid] = chb[tid] + g_S[2 * br][tid];
            s1v[tid] = g_S[2 * br + 1][tid];
        }
        if (tid < 16) ws[tid] = g_wsum[br][tid];
        __syncthreads();

        const int lane = tid & 31, rp = tid >> 5;
        const int h = hc * 32 + lane;
        const int R = V * GO;
        const int RP = R >> 3;
        float acc = 0.f;
#pragma unroll 4
        for (int r = rp * RP; r < (rp + 1) * RP; r++) {
            int o = r & 63, v = r >> 6;
            float coef = cfo[o] + s1v[o] * ws[v];
            acc += coef * P[r * H + h];
        }
        red[tid] = acc;
        __syncthreads();
        if (tid < 32) {
            float s = pb[h];
#pragma unroll
            for (int j = 0; j < 8; j++) s += red[j * 32 + lane];
            g_C[br][h] = s;
        }
    }
}

// ------- main: fp16 HMMA GEMM, MT=32, 512 threads (16 warps), gated tail -----
extern __shared__ char smx[];

__global__ void __launch_bounds__(NTHR, 1)
k_main(const float* __restrict__ ecc, const float* __restrict__ err,
       const float* __restrict__ attnW, const float* __restrict__ attnb,
       const float* __restrict__ fc2W, const float* __restrict__ fc2b,
       float* __restrict__ out) {
    char* sXf = smx + XF_OFS;
    char* sBf = smx + BF_OFS;

    const int tid = threadIdx.x;
    const int wid = tid >> 5;       // 0..15
    const int lane = tid & 31;
    const int g = lane >> 2;        // fragment group row/col
    const int i2 = (lane & 3) * 2;  // fragment k pair base
    const int ns = wid * 16;        // this warp's 16-col n slice
    const int rb = blockIdx.x * MT;

    float de[2][2][4], dr[2][2][4];
#pragma unroll
    for (int mt = 0; mt < 2; mt++)
#pragma unroll
        for (int nt = 0; nt < 2; nt++)
#pragma unroll
            for (int j = 0; j < 4; j++) {
                de[mt][nt][j] = 0.f;
                dr[mt][nt][j] = 0.f;
            }

#pragma unroll 1
    for (int c = 0; c < NCH; c++) {
        const int br = (c >= NCHE);
        const int cc = br ? c - NCHE : c;
        const float* X = br ? err : ecc;
        const int Kreal = br ? KR : KE;
        const int KP = br ? KPR : KPE;
        const char* gB = (const char*)(g_Bf + (br ? B_ERR_OFS : 0));

        __syncthreads();   // previous chunk's mma reads done
        // ---- stage X chunk: 32 rows x 64 k, fp32 -> fp16 (512 items) ----
        {
            int row = tid >> 4, kq = tid & 15;
            int k = cc * KC + kq * 4;
            float4 x = make_float4(0.f, 0.f, 0.f, 0.f);
            if (k < Kreal)
                x = *(const float4*)&X[(size_t)(rb + row) * Kreal + k];
            *(uint2*)(sXf + row * RSB + kq * 8) =
                make_uint2(pack_h2(__float2half_rn(x.x), __float2half_rn(x.y)),
                           pack_h2(__float2half_rn(x.z), __float2half_rn(x.w)));
        }
        // ---- stage B chunk: 256 n x 64 k fp16, 16B copies (2048 items) ----
#pragma unroll
        for (int it = 0; it < 4; it++) {
            int idx = tid + it * NTHR;
            int n = idx >> 3, q = idx & 7;
            size_t gb = (size_t)n * KP * 2 + (size_t)cc * KC * 2 + q * 16;
            *(uint4*)(sBf + n * RSB + q * 16) = *(const uint4*)(gB + gb);
        }
        __syncthreads();

        float (*d)[2][4] = br ? dr : de;
        // ---- 4 k-steps of m16n8k16 fp16 ----
#pragma unroll
        for (int ks = 0; ks < 4; ks++) {
            const int kb = ks * 32 + i2 * 2;
            uint32_t a[2][4];
#pragma unroll
            for (int mt = 0; mt < 2; mt++) {
                const char* ap = sXf + (mt * 16 + g) * RSB + kb;
                a[mt][0] = *(const uint32_t*)ap;
                a[mt][1] = *(const uint32_t*)(ap + 8 * RSB);
                a[mt][2] = *(const uint32_t*)(ap + 16);
                a[mt][3] = *(const uint32_t*)(ap + 8 * RSB + 16);
            }
#pragma unroll
            for (int nt = 0; nt < 2; nt++) {
                const char* bp = sBf + (ns + nt * 8 + g) * RSB + kb;
                uint32_t b0 = *(const uint32_t*)bp;
                uint32_t b1 = *(const uint32_t*)(bp + 16);
#pragma unroll
                for (int mt = 0; mt < 2; mt++)
                    mma16816(d[mt][nt], a[mt][0], a[mt][1], a[mt][2], a[mt][3],
                             b0, b1);
            }
        }
    }
    __syncthreads();

    // -------- write fragments to smem (reuse staging buffer) --------
    float* eg = (float*)smx;
    float* rg = eg + MT * ES;
#pragma unroll
    for (int mt = 0; mt < 2; mt++)
#pragma unroll
        for (int nt = 0; nt < 2; nt++) {
            int row = mt * 16 + g;
            int col = ns + nt * 8 + i2;
            eg[row * ES + col] = de[mt][nt][0];
            eg[row * ES + col + 1] = de[mt][nt][1];
            eg[(row + 8) * ES + col] = de[mt][nt][2];
            eg[(row + 8) * ES + col + 1] = de[mt][nt][3];
            rg[row * ES + col] = dr[mt][nt][0];
            rg[row * ES + col + 1] = dr[mt][nt][1];
            rg[(row + 8) * ES + col] = dr[mt][nt][2];
            rg[(row + 8) * ES + col + 1] = dr[mt][nt][3];
        }
    __syncthreads();

    // -------- gated tail: 1 warp per 2 rows (16 warps x 2 = 32 rows) --------
    const float attnb_v = attnb[0];
    const float fc2b_v = fc2b[0];
    for (int r = wid * 2; r < wid * 2 + 2; r++) {
        const float* egr = eg + r * ES;
        const float* rgr = rg + r * ES;
        float p = 0.f;
#pragma unroll
        for (int j = lane; j < H; j += 32) {
            float ev = egr[j] + g_C[0][j];
            float rv = rgr[j] + g_C[1][j];
            p += tanhf(ev + rv) * attnW[j];
        }
#pragma unroll
        for (int o = 16; o; o >>= 1) p += __shfl_xor_sync(0xffffffffu, p, o);
        float attn = 1.f / (1.f + expf(-(p + attnb_v)));
        float q = 0.f;
#pragma unroll
        for (int j = lane; j < H; j += 32) {
            float ev = egr[j] + g_C[0][j];
            float rv = rgr[j] + g_C[1][j];
            float f = attn * ev + (1.f - attn) * rv;
            q += fmaxf(f, 0.f) * fc2W[j];
        }
#pragma unroll
        for (int o = 16; o; o >>= 1) q += __shfl_xor_sync(0xffffffffu, q, o);
        if (lane == 0) out[rb + r] = 1.f / (1.f + expf(-(q + fc2b_v)));
    }
}

// ---------------- launch ----------------
extern "C" void kernel_launch(void* const* d_in, const int* in_sizes, int n_in,
                              void* d_out, int out_size) {
    const float* ecc = (const float*)d_in[0];
    const float* err = (const float*)d_in[1];
    const float* conv_ecc_w = (const float*)d_in[2];
    const float* conv_ecc_b = (const float*)d_in[3];
    const float* conv_err_w = (const float*)d_in[4];
    const float* conv_err_b = (const float*)d_in[5];
    const float* cheb_ecc_W = (const float*)d_in[6];
    const float* cheb_ecc_b = (const float*)d_in[7];
    const float* cheb_err_W = (const float*)d_in[8];
    const float* cheb_err_b = (const float*)d_in[9];
    const float* ecc_proj_W = (const float*)d_in[10];
    const float* ecc_proj_b = (const float*)d_in[11];
    const float* err_proj_W = (const float*)d_in[12];
    const float* err_proj_b = (const float*)d_in[13];
    const float* attn_W = (const float*)d_in[14];
    const float* attn_b = (const float*)d_in[15];
    const float* fc2_W = (const float*)d_in[16];
    const float* fc2_b = (const float*)d_in[17];
    const int* ei_ecc = (const int*)d_in[18];
    const int* ei_err = (const int*)d_in[19];
    const int Ee = in_sizes[18] / 2;
    const int Er = in_sizes[19] / 2;

    k_prep<<<4 * T + 5, 256>>>(conv_ecc_w, conv_ecc_b, conv_err_w, conv_err_b,
                               cheb_ecc_W, cheb_err_W, ei_ecc, Ee, ei_err, Er);
    k_AC<<<(VE + VR) * 4 + 17, 256>>>(ecc_proj_W, err_proj_W,
                                      ecc_proj_b, err_proj_b,
                                      cheb_ecc_b, cheb_err_b);

    cudaFuncSetAttribute(k_main, cudaFuncAttributeMaxDynamicSharedMemorySize,
                         SM_MAIN);
    k_main<<<BATCH / MT, NTHR, SM_MAIN>>>(ecc, err, attn_W, attn_b,
                                          fc2_W, fc2_b, (float*)d_out);
}